// round 7
// baseline (speedup 1.0000x reference)
#include <cuda_runtime.h>
#include <cuda_fp16.h>
#include <cstdint>

// out[1024,4096] = tanh(x[1024,8192] @ scatter(W[8192,4096]) + bias)
// sm_100 base target (no tcgen05): cp.async + mma.sync.m16n8k16.f16.f32.
// R6 profile: tensor=50.4%, occ=12.5% -> latency-bound at 2 warps/SMSP.
// This round: 512 threads / 16 warps (4 warps/SMSP), warp tile 32x64,
// 64 accs/thread (~120 regs). Memset restored (clear-kernel was -26us worse).

#define D_DIM 8192
#define U_DIM 4096
#define B_ROWS 1024

#define MT 128
#define NT 256
#define KC 64
#define PITCH 72                           // halves per smem row (pad 64->72)
#define A_ST (MT * PITCH)                  // 9216 halves
#define B_ST (NT * PITCH)                  // 18432 halves
#define STG_H (A_ST + B_ST)                // 27648 halves
#define N_STAGES 4
#define SMEM_DYN (N_STAGES * STG_H * 2)    // 221184 B
#define N_ITER (D_DIM / KC)                // 128

__device__ __half g_W[(size_t)U_DIM * D_DIM];  // Wt[u][d], 64 MB
__device__ __half g_X[(size_t)B_ROWS * D_DIM]; // fp16 x, 16 MB

// ---------------------------------------------------------------- helpers
__device__ __forceinline__ uint32_t smem_u32(const void* p) {
    uint32_t a;
    asm("{ .reg .u64 t; cvta.to.shared.u64 t, %1; cvt.u32.u64 %0, t; }"
        : "=r"(a) : "l"(p));
    return a;
}

__device__ __forceinline__ void mma_f16(float* c, const uint32_t* a, const uint32_t* b) {
    asm volatile(
        "mma.sync.aligned.m16n8k16.row.col.f32.f16.f16.f32 "
        "{%0,%1,%2,%3}, {%4,%5,%6,%7}, {%8,%9}, {%0,%1,%2,%3};"
        : "+f"(c[0]), "+f"(c[1]), "+f"(c[2]), "+f"(c[3])
        : "r"(a[0]), "r"(a[1]), "r"(a[2]), "r"(a[3]), "r"(b[0]), "r"(b[1]));
}

#define CP_ASYNC16(sm, gp) \
    asm volatile("cp.async.cg.shared.global [%0], [%1], 16;" \
                 :: "r"(sm), "l"(gp) : "memory")
#define CP_COMMIT()  asm volatile("cp.async.commit_group;" ::: "memory")
#define CP_WAIT2()   asm volatile("cp.async.wait_group 2;" ::: "memory")

// ---------------------------------------------------------------- pre-passes
__global__ void conv_x_kernel(const float4* __restrict__ in, uint2* __restrict__ outp, int n4) {
    int i = blockIdx.x * blockDim.x + threadIdx.x;
    if (i < n4) {
        float4 v = in[i];
        __half2 lo = __floats2half2_rn(v.x, v.y);
        __half2 hi = __floats2half2_rn(v.z, v.w);
        outp[i] = make_uint2(*(uint32_t*)&lo, *(uint32_t*)&hi);
    }
}

__global__ void scatter_kernel(const int2* __restrict__ ind, const float* __restrict__ val,
                               __half* __restrict__ W, int nnz) {
    int i = blockIdx.x * blockDim.x + threadIdx.x;
    if (i < nnz) {
        int2 du = ind[i];  // .x = d (row of dense W), .y = u (col)
        atomicAdd(W + ((size_t)du.y * D_DIM + du.x), __float2half(val[i]));
    }
}

// ---------------------------------------------------------------- GEMM
__global__ void __launch_bounds__(512, 1)
sparse_gemm_kernel(const __half* __restrict__ gA,   // g_X [1024][8192]
                   const __half* __restrict__ gB,   // g_W [4096][8192]
                   const float* __restrict__ bias,
                   float* __restrict__ out) {
    extern __shared__ __half smem[];
    uint32_t sbase = smem_u32(smem);

    const int tid  = threadIdx.x;
    const int lane = tid & 31;
    const int wid  = tid >> 5;
    const int wm   = wid >> 2;        // 0..3 -> rows wm*32
    const int wn   = wid & 3;         // 0..3 -> cols wn*64
    const int mt = blockIdx.x & 7;    // consecutive bx share an N-tile (W L2 reuse)
    const int nt = blockIdx.x >> 3;
    const int m0 = mt * MT, n0 = nt * NT;

    float acc[2][8][4];
#pragma unroll
    for (int f = 0; f < 2; f++)
#pragma unroll
        for (int bf = 0; bf < 8; bf++)
#pragma unroll
            for (int k = 0; k < 4; k++) acc[f][bf][k] = 0.f;

    // ---- stage loader: 128x64 A + 256x64 B halves, 16B chunks, 6/thread ----
    auto stage_load = [&](int s, int kt) {
        uint32_t sA = sbase + (uint32_t)(s * STG_H) * 2u;
        uint32_t sB = sA + (uint32_t)A_ST * 2u;
        const __half* ga = gA + (size_t)m0 * D_DIM + kt * KC;
        const __half* gb = gB + (size_t)n0 * D_DIM + kt * KC;
#pragma unroll
        for (int i = 0; i < 2; i++) {                 // A: 1024 chunks
            int ch = tid + i * 512, row = ch >> 3, cc = ch & 7;
            CP_ASYNC16(sA + (uint32_t)(row * PITCH + cc * 8) * 2u,
                       ga + (size_t)row * D_DIM + cc * 8);
        }
#pragma unroll
        for (int i = 0; i < 4; i++) {                 // B: 2048 chunks
            int ch = tid + i * 512, row = ch >> 3, cc = ch & 7;
            CP_ASYNC16(sB + (uint32_t)(row * PITCH + cc * 8) * 2u,
                       gb + (size_t)row * D_DIM + cc * 8);
        }
    };

#pragma unroll
    for (int s = 0; s < 3; s++) { stage_load(s, s); CP_COMMIT(); }

    for (int it = 0; it < N_ITER; it++) {
        const int s = it & (N_STAGES - 1);
        CP_WAIT2();
        __syncthreads();
        if (it + 3 < N_ITER) stage_load((it + 3) & (N_STAGES - 1), it + 3);
        CP_COMMIT();

        const __half* sA = smem + s * STG_H;
        const __half* sB = sA + A_ST;
        const int rA = wm * 32 + (lane >> 2);         // A frag base row
        const int nB = wn * 64 + (lane >> 2);         // B frag base col
        const int kt = (lane & 3) * 2;                // k offset within step
#pragma unroll
        for (int kk = 0; kk < 4; kk++) {
            const int k0 = kk * 16 + kt;
            uint32_t a[2][4];
#pragma unroll
            for (int f = 0; f < 2; f++) {
                const __half* ar = sA + (rA + f * 16) * PITCH + k0;
                a[f][0] = *(const uint32_t*)(ar);
                a[f][1] = *(const uint32_t*)(ar + 8 * PITCH);
                a[f][2] = *(const uint32_t*)(ar + 8);
                a[f][3] = *(const uint32_t*)(ar + 8 * PITCH + 8);
            }
#pragma unroll
            for (int bf = 0; bf < 8; bf++) {
                const __half* br = sB + (nB + bf * 8) * PITCH + k0;
                uint32_t b[2];
                b[0] = *(const uint32_t*)(br);
                b[1] = *(const uint32_t*)(br + 8);
                mma_f16(acc[0][bf], a[0], b);
                mma_f16(acc[1][bf], a[1], b);
            }
        }
    }

    // ---- epilogue: bias + tanh, float2 stores ----
#pragma unroll
    for (int f = 0; f < 2; f++) {
        const int r0 = m0 + wm * 32 + f * 16 + (lane >> 2);
#pragma unroll
        for (int bf = 0; bf < 8; bf++) {
            const int cb = n0 + wn * 64 + bf * 8 + 2 * (lane & 3);
            const float b0 = __ldg(bias + cb), b1 = __ldg(bias + cb + 1);
            float2 v0 = {tanhf(acc[f][bf][0] + b0), tanhf(acc[f][bf][1] + b1)};
            float2 v1 = {tanhf(acc[f][bf][2] + b0), tanhf(acc[f][bf][3] + b1)};
            *(float2*)(out + (size_t)r0 * U_DIM + cb) = v0;
            *(float2*)(out + (size_t)(r0 + 8) * U_DIM + cb) = v1;
        }
    }
}

// ---------------------------------------------------------------- host side
extern "C" void kernel_launch(void* const* d_in, const int* in_sizes, int n_in,
                              void* d_out, int out_size) {
    const float* x    = (const float*)d_in[0];
    const float* kv   = (const float*)d_in[1];
    const float* bias = (const float*)d_in[2];
    const int*   ind  = (const int*)d_in[3];
    float* out = (float*)d_out;
    int nnz = in_sizes[1];

    void* wptr = nullptr;
    void* xptr = nullptr;
    cudaGetSymbolAddress(&wptr, g_W);
    cudaGetSymbolAddress(&xptr, g_X);

    cudaFuncSetAttribute(sparse_gemm_kernel,
                         cudaFuncAttributeMaxDynamicSharedMemorySize, SMEM_DYN);

    cudaMemsetAsync(wptr, 0, (size_t)U_DIM * D_DIM * sizeof(__half));

    int n4 = B_ROWS * D_DIM / 4;
    conv_x_kernel<<<(n4 + 255) / 256, 256>>>((const float4*)x, (uint2*)xptr, n4);

    scatter_kernel<<<(nnz + 255) / 256, 256>>>((const int2*)ind, kv, (__half*)wptr, nnz);

    sparse_gemm_kernel<<<(B_ROWS / MT) * (U_DIM / NT), 512, SMEM_DYN>>>(
        (const __half*)xptr, (const __half*)wptr, bias, out);
}

// round 8
// speedup vs baseline: 1.0474x; 1.0474x over previous
#include <cuda_runtime.h>
#include <cuda_fp16.h>
#include <cstdint>

// out[1024,4096] = tanh(x[1024,8192] @ scatter(W[8192,4096]) + bias)
// sm_100 base target (no tcgen05): cp.async + ldmatrix + mma.m16n8k16.f16.f32.
// R6 model (validated): rt_HMMA=8/SMSP (1024 MAC/cyc/SM); 3860 cyc/iter at a
// 2048 floor -> ~1800 cyc of LDS/issue overhead. R7's 16-warp attempt raised
// LDS/MMA and regressed. This round: R6 shape + ldmatrix.x4 (128 LDS.32 ->
// 32 ldmatrix per warp/iter).

#define D_DIM 8192
#define U_DIM 4096
#define B_ROWS 1024

#define MT 128
#define NT 256
#define KC 64
#define PITCH 72                           // halves per smem row (144 B, 16B-aligned)
#define A_ST (MT * PITCH)                  // 9216 halves
#define B_ST (NT * PITCH)                  // 18432 halves
#define STG_H (A_ST + B_ST)                // 27648 halves
#define N_STAGES 4
#define SMEM_DYN (N_STAGES * STG_H * 2)    // 221184 B
#define N_ITER (D_DIM / KC)                // 128

__device__ __half g_W[(size_t)U_DIM * D_DIM];  // Wt[u][d], 64 MB
__device__ __half g_X[(size_t)B_ROWS * D_DIM]; // fp16 x, 16 MB

// ---------------------------------------------------------------- helpers
__device__ __forceinline__ uint32_t smem_u32(const void* p) {
    uint32_t a;
    asm("{ .reg .u64 t; cvta.to.shared.u64 t, %1; cvt.u32.u64 %0, t; }"
        : "=r"(a) : "l"(p));
    return a;
}

__device__ __forceinline__ void mma_f16(float* c, const uint32_t* a, const uint32_t* b) {
    asm volatile(
        "mma.sync.aligned.m16n8k16.row.col.f32.f16.f16.f32 "
        "{%0,%1,%2,%3}, {%4,%5,%6,%7}, {%8,%9}, {%0,%1,%2,%3};"
        : "+f"(c[0]), "+f"(c[1]), "+f"(c[2]), "+f"(c[3])
        : "r"(a[0]), "r"(a[1]), "r"(a[2]), "r"(a[3]), "r"(b[0]), "r"(b[1]));
}

#define LDMATRIX_X4(r0, r1, r2, r3, addr) \
    asm volatile("ldmatrix.sync.aligned.m8n8.x4.shared.b16 {%0,%1,%2,%3}, [%4];" \
                 : "=r"(r0), "=r"(r1), "=r"(r2), "=r"(r3) : "r"(addr))

#define CP_ASYNC16(sm, gp) \
    asm volatile("cp.async.cg.shared.global [%0], [%1], 16;" \
                 :: "r"(sm), "l"(gp) : "memory")
#define CP_COMMIT()  asm volatile("cp.async.commit_group;" ::: "memory")
#define CP_WAIT2()   asm volatile("cp.async.wait_group 2;" ::: "memory")

// ---------------------------------------------------------------- pre-passes
__global__ void conv_x_kernel(const float4* __restrict__ in, uint2* __restrict__ outp, int n4) {
    int i = blockIdx.x * blockDim.x + threadIdx.x;
    if (i < n4) {
        float4 v = in[i];
        __half2 lo = __floats2half2_rn(v.x, v.y);
        __half2 hi = __floats2half2_rn(v.z, v.w);
        outp[i] = make_uint2(*(uint32_t*)&lo, *(uint32_t*)&hi);
    }
}

__global__ void scatter_kernel(const int2* __restrict__ ind, const float* __restrict__ val,
                               __half* __restrict__ W, int nnz) {
    int i = blockIdx.x * blockDim.x + threadIdx.x;
    if (i < nnz) {
        int2 du = ind[i];  // .x = d (row of dense W), .y = u (col)
        atomicAdd(W + ((size_t)du.y * D_DIM + du.x), __float2half(val[i]));
    }
}

// ---------------------------------------------------------------- GEMM
__global__ void __launch_bounds__(256, 1)
sparse_gemm_kernel(const __half* __restrict__ gA,   // g_X [1024][8192]
                   const __half* __restrict__ gB,   // g_W [4096][8192]
                   const float* __restrict__ bias,
                   float* __restrict__ out) {
    extern __shared__ __half smem[];
    uint32_t sbase = smem_u32(smem);

    const int tid  = threadIdx.x;
    const int lane = tid & 31;
    const int wid  = tid >> 5;
    const int wm   = wid >> 2;        // 0..1 -> rows wm*64
    const int wn   = wid & 3;         // 0..3 -> cols wn*64
    const int mt = blockIdx.x & 7;    // consecutive bx share an N-tile (W L2 reuse)
    const int nt = blockIdx.x >> 3;
    const int m0 = mt * MT, n0 = nt * NT;

    // ldmatrix per-thread row/col selectors (byte offsets within a stage):
    //  A x4 mats: m0..7/k0 | m8..15/k0 | m0..7/k8 | m8..15/k8 -> a0..a3
    const int am = (((lane >> 3) & 1) << 3) + (lane & 7);
    const int ak = (lane >> 4) << 3;
    //  B x4 mats: n0..7/k0 | n0..7/k8 | n8..15/k0 | n8..15/k8 -> bfE.b0,bfE.b1,bfO.b0,bfO.b1
    const int bn = ((lane >> 4) << 3) + (lane & 7);
    const int bk = (((lane >> 3) & 1)) << 3;

    uint32_t aoff[4], boff[4];
#pragma unroll
    for (int f = 0; f < 4; f++)
        aoff[f] = (uint32_t)(((wm * 64 + f * 16 + am) * PITCH + ak) * 2);
#pragma unroll
    for (int p = 0; p < 4; p++)
        boff[p] = (uint32_t)(A_ST * 2 + ((wn * 64 + p * 16 + bn) * PITCH + bk) * 2);

    float acc[4][8][4];
#pragma unroll
    for (int f = 0; f < 4; f++)
#pragma unroll
        for (int bf = 0; bf < 8; bf++)
#pragma unroll
            for (int k = 0; k < 4; k++) acc[f][bf][k] = 0.f;

    // ---- stage loader: 128x64 A + 256x64 B halves, 16B chunks, 12/thread ----
    auto stage_load = [&](int s, int kt) {
        uint32_t sA = sbase + (uint32_t)(s * STG_H) * 2u;
        uint32_t sB = sA + (uint32_t)A_ST * 2u;
        const __half* ga = gA + (size_t)m0 * D_DIM + kt * KC;
        const __half* gb = gB + (size_t)n0 * D_DIM + kt * KC;
#pragma unroll
        for (int i = 0; i < 4; i++) {                 // A: 1024 chunks
            int ch = tid + i * 256, row = ch >> 3, cc = ch & 7;
            CP_ASYNC16(sA + (uint32_t)(row * PITCH + cc * 8) * 2u,
                       ga + (size_t)row * D_DIM + cc * 8);
        }
#pragma unroll
        for (int i = 0; i < 8; i++) {                 // B: 2048 chunks
            int ch = tid + i * 256, row = ch >> 3, cc = ch & 7;
            CP_ASYNC16(sB + (uint32_t)(row * PITCH + cc * 8) * 2u,
                       gb + (size_t)row * D_DIM + cc * 8);
        }
    };

#pragma unroll
    for (int s = 0; s < 3; s++) { stage_load(s, s); CP_COMMIT(); }

    for (int it = 0; it < N_ITER; it++) {
        const int s = it & (N_STAGES - 1);
        CP_WAIT2();
        __syncthreads();
        if (it + 3 < N_ITER) stage_load((it + 3) & (N_STAGES - 1), it + 3);
        CP_COMMIT();

        const uint32_t stg = sbase + (uint32_t)(s * STG_H) * 2u;
#pragma unroll
        for (int kk = 0; kk < 4; kk++) {
            const uint32_t kb = (uint32_t)(kk * 16 * 2);   // 32 B per k-step
            uint32_t a[4][4], b[4][4];
#pragma unroll
            for (int f = 0; f < 4; f++)
                LDMATRIX_X4(a[f][0], a[f][1], a[f][2], a[f][3], stg + aoff[f] + kb);
#pragma unroll
            for (int p = 0; p < 4; p++)
                LDMATRIX_X4(b[p][0], b[p][1], b[p][2], b[p][3], stg + boff[p] + kb);
#pragma unroll
            for (int bf = 0; bf < 8; bf++)
#pragma unroll
                for (int f = 0; f < 4; f++)
                    mma_f16(acc[f][bf], a[f], &b[bf >> 1][(bf & 1) << 1]);
        }
    }

    // ---- epilogue: bias + tanh, float2 stores ----
#pragma unroll
    for (int f = 0; f < 4; f++) {
        const int r0 = m0 + wm * 64 + f * 16 + (lane >> 2);
#pragma unroll
        for (int bf = 0; bf < 8; bf++) {
            const int cb = n0 + wn * 64 + bf * 8 + 2 * (lane & 3);
            const float b0 = __ldg(bias + cb), b1 = __ldg(bias + cb + 1);
            float2 v0 = {tanhf(acc[f][bf][0] + b0), tanhf(acc[f][bf][1] + b1)};
            float2 v1 = {tanhf(acc[f][bf][2] + b0), tanhf(acc[f][bf][3] + b1)};
            *(float2*)(out + (size_t)r0 * U_DIM + cb) = v0;
            *(float2*)(out + (size_t)(r0 + 8) * U_DIM + cb) = v1;
        }
    }
}

// ---------------------------------------------------------------- host side
extern "C" void kernel_launch(void* const* d_in, const int* in_sizes, int n_in,
                              void* d_out, int out_size) {
    const float* x    = (const float*)d_in[0];
    const float* kv   = (const float*)d_in[1];
    const float* bias = (const float*)d_in[2];
    const int*   ind  = (const int*)d_in[3];
    float* out = (float*)d_out;
    int nnz = in_sizes[1];

    void* wptr = nullptr;
    void* xptr = nullptr;
    cudaGetSymbolAddress(&wptr, g_W);
    cudaGetSymbolAddress(&xptr, g_X);

    cudaFuncSetAttribute(sparse_gemm_kernel,
                         cudaFuncAttributeMaxDynamicSharedMemorySize, SMEM_DYN);

    cudaMemsetAsync(wptr, 0, (size_t)U_DIM * D_DIM * sizeof(__half));

    int n4 = B_ROWS * D_DIM / 4;
    conv_x_kernel<<<(n4 + 255) / 256, 256>>>((const float4*)x, (uint2*)xptr, n4);

    scatter_kernel<<<(nnz + 255) / 256, 256>>>((const int2*)ind, kv, (__half*)wptr, nnz);

    sparse_gemm_kernel<<<(B_ROWS / MT) * (U_DIM / NT), 256, SMEM_DYN>>>(
        (const __half*)xptr, (const __half*)wptr, bias, out);
}

// round 9
// speedup vs baseline: 1.0529x; 1.0052x over previous
#include <cuda_runtime.h>
#include <cuda_fp16.h>
#include <cstdint>

// out[1024,4096] = tanh(x[1024,8192] @ scatter(W[8192,4096]) + bias)
// sm_100 base target (no tcgen05): cp.async + ldmatrix + mma.m16n8k16.f16.f32.
// R8 lesson: LDS *count* wasn't the bottleneck (4x fewer shared ops -> ~same
// time). Theory: load-phase/MMA-phase serialization exposed at 2 warps/SMSP.
// This round: software-pipelined (double-buffered) fragment loads — issue
// k-step kk+1's ldmatrix before kk's MMAs.

#define D_DIM 8192
#define U_DIM 4096
#define B_ROWS 1024

#define MT 128
#define NT 256
#define KC 64
#define PITCH 72                           // halves per smem row (144 B, 16B-aligned)
#define A_ST (MT * PITCH)                  // 9216 halves
#define B_ST (NT * PITCH)                  // 18432 halves
#define STG_H (A_ST + B_ST)                // 27648 halves
#define N_STAGES 4
#define SMEM_DYN (N_STAGES * STG_H * 2)    // 221184 B
#define N_ITER (D_DIM / KC)                // 128

__device__ __half g_W[(size_t)U_DIM * D_DIM];  // Wt[u][d], 64 MB
__device__ __half g_X[(size_t)B_ROWS * D_DIM]; // fp16 x, 16 MB

// ---------------------------------------------------------------- helpers
__device__ __forceinline__ uint32_t smem_u32(const void* p) {
    uint32_t a;
    asm("{ .reg .u64 t; cvta.to.shared.u64 t, %1; cvt.u32.u64 %0, t; }"
        : "=r"(a) : "l"(p));
    return a;
}

__device__ __forceinline__ void mma_f16(float* c, const uint32_t* a, const uint32_t* b) {
    asm volatile(
        "mma.sync.aligned.m16n8k16.row.col.f32.f16.f16.f32 "
        "{%0,%1,%2,%3}, {%4,%5,%6,%7}, {%8,%9}, {%0,%1,%2,%3};"
        : "+f"(c[0]), "+f"(c[1]), "+f"(c[2]), "+f"(c[3])
        : "r"(a[0]), "r"(a[1]), "r"(a[2]), "r"(a[3]), "r"(b[0]), "r"(b[1]));
}

#define LDMATRIX_X4(r0, r1, r2, r3, addr) \
    asm volatile("ldmatrix.sync.aligned.m8n8.x4.shared.b16 {%0,%1,%2,%3}, [%4];" \
                 : "=r"(r0), "=r"(r1), "=r"(r2), "=r"(r3) : "r"(addr))

#define CP_ASYNC16(sm, gp) \
    asm volatile("cp.async.cg.shared.global [%0], [%1], 16;" \
                 :: "r"(sm), "l"(gp) : "memory")
#define CP_COMMIT()  asm volatile("cp.async.commit_group;" ::: "memory")
#define CP_WAIT2()   asm volatile("cp.async.wait_group 2;" ::: "memory")

// ---------------------------------------------------------------- pre-passes
__global__ void conv_x_kernel(const float4* __restrict__ in, uint2* __restrict__ outp, int n4) {
    int i = blockIdx.x * blockDim.x + threadIdx.x;
    if (i < n4) {
        float4 v = in[i];
        __half2 lo = __floats2half2_rn(v.x, v.y);
        __half2 hi = __floats2half2_rn(v.z, v.w);
        outp[i] = make_uint2(*(uint32_t*)&lo, *(uint32_t*)&hi);
    }
}

__global__ void scatter_kernel(const int2* __restrict__ ind, const float* __restrict__ val,
                               __half* __restrict__ W, int nnz) {
    int i = blockIdx.x * blockDim.x + threadIdx.x;
    if (i < nnz) {
        int2 du = ind[i];  // .x = d (row of dense W), .y = u (col)
        atomicAdd(W + ((size_t)du.y * D_DIM + du.x), __float2half(val[i]));
    }
}

// ---------------------------------------------------------------- GEMM
__global__ void __launch_bounds__(256, 1)
sparse_gemm_kernel(const __half* __restrict__ gA,   // g_X [1024][8192]
                   const __half* __restrict__ gB,   // g_W [4096][8192]
                   const float* __restrict__ bias,
                   float* __restrict__ out) {
    extern __shared__ __half smem[];
    uint32_t sbase = smem_u32(smem);

    const int tid  = threadIdx.x;
    const int lane = tid & 31;
    const int wid  = tid >> 5;
    const int wm   = wid >> 2;        // 0..1 -> rows wm*64
    const int wn   = wid & 3;         // 0..3 -> cols wn*64
    const int mt = blockIdx.x & 7;    // consecutive bx share an N-tile (W L2 reuse)
    const int nt = blockIdx.x >> 3;
    const int m0 = mt * MT, n0 = nt * NT;

    // ldmatrix per-thread selectors (byte offsets within a stage)
    const int am = (((lane >> 3) & 1) << 3) + (lane & 7);
    const int ak = (lane >> 4) << 3;
    const int bn = ((lane >> 4) << 3) + (lane & 7);
    const int bk = (((lane >> 3) & 1)) << 3;

    uint32_t aoff[4], boff[4];
#pragma unroll
    for (int f = 0; f < 4; f++)
        aoff[f] = (uint32_t)(((wm * 64 + f * 16 + am) * PITCH + ak) * 2);
#pragma unroll
    for (int p = 0; p < 4; p++)
        boff[p] = (uint32_t)(A_ST * 2 + ((wn * 64 + p * 16 + bn) * PITCH + bk) * 2);

    float acc[4][8][4];
#pragma unroll
    for (int f = 0; f < 4; f++)
#pragma unroll
        for (int bf = 0; bf < 8; bf++)
#pragma unroll
            for (int k = 0; k < 4; k++) acc[f][bf][k] = 0.f;

    // ---- stage loader: 128x64 A + 256x64 B halves, 16B chunks, 12/thread ----
    auto stage_load = [&](int s, int kt) {
        uint32_t sA = sbase + (uint32_t)(s * STG_H) * 2u;
        uint32_t sB = sA + (uint32_t)A_ST * 2u;
        const __half* ga = gA + (size_t)m0 * D_DIM + kt * KC;
        const __half* gb = gB + (size_t)n0 * D_DIM + kt * KC;
#pragma unroll
        for (int i = 0; i < 4; i++) {                 // A: 1024 chunks
            int ch = tid + i * 256, row = ch >> 3, cc = ch & 7;
            CP_ASYNC16(sA + (uint32_t)(row * PITCH + cc * 8) * 2u,
                       ga + (size_t)row * D_DIM + cc * 8);
        }
#pragma unroll
        for (int i = 0; i < 8; i++) {                 // B: 2048 chunks
            int ch = tid + i * 256, row = ch >> 3, cc = ch & 7;
            CP_ASYNC16(sB + (uint32_t)(row * PITCH + cc * 8) * 2u,
                       gb + (size_t)row * D_DIM + cc * 8);
        }
    };

#pragma unroll
    for (int s = 0; s < 3; s++) { stage_load(s, s); CP_COMMIT(); }

    for (int it = 0; it < N_ITER; it++) {
        const int s = it & (N_STAGES - 1);
        CP_WAIT2();
        __syncthreads();
        if (it + 3 < N_ITER) stage_load((it + 3) & (N_STAGES - 1), it + 3);
        CP_COMMIT();

        const uint32_t stg = sbase + (uint32_t)(s * STG_H) * 2u;

        // software-pipelined frags: load kk+1 before kk's MMAs
        uint32_t a[2][4][4], b[2][4][4];
#pragma unroll
        for (int f = 0; f < 4; f++)
            LDMATRIX_X4(a[0][f][0], a[0][f][1], a[0][f][2], a[0][f][3], stg + aoff[f]);
#pragma unroll
        for (int p = 0; p < 4; p++)
            LDMATRIX_X4(b[0][p][0], b[0][p][1], b[0][p][2], b[0][p][3], stg + boff[p]);

#pragma unroll
        for (int kk = 0; kk < 4; kk++) {
            const int cur = kk & 1, nxt = cur ^ 1;
            if (kk < 3) {
                const uint32_t kb = (uint32_t)((kk + 1) * 32);   // 32 B per k-step
#pragma unroll
                for (int f = 0; f < 4; f++)
                    LDMATRIX_X4(a[nxt][f][0], a[nxt][f][1], a[nxt][f][2], a[nxt][f][3],
                                stg + aoff[f] + kb);
#pragma unroll
                for (int p = 0; p < 4; p++)
                    LDMATRIX_X4(b[nxt][p][0], b[nxt][p][1], b[nxt][p][2], b[nxt][p][3],
                                stg + boff[p] + kb);
            }
#pragma unroll
            for (int bf = 0; bf < 8; bf++)
#pragma unroll
                for (int f = 0; f < 4; f++)
                    mma_f16(acc[f][bf], a[cur][f], &b[cur][bf >> 1][(bf & 1) << 1]);
        }
    }

    // ---- epilogue: bias + tanh, float2 stores ----
#pragma unroll
    for (int f = 0; f < 4; f++) {
        const int r0 = m0 + wm * 64 + f * 16 + (lane >> 2);
#pragma unroll
        for (int bf = 0; bf < 8; bf++) {
            const int cb = n0 + wn * 64 + bf * 8 + 2 * (lane & 3);
            const float b0 = __ldg(bias + cb), b1 = __ldg(bias + cb + 1);
            float2 v0 = {tanhf(acc[f][bf][0] + b0), tanhf(acc[f][bf][1] + b1)};
            float2 v1 = {tanhf(acc[f][bf][2] + b0), tanhf(acc[f][bf][3] + b1)};
            *(float2*)(out + (size_t)r0 * U_DIM + cb) = v0;
            *(float2*)(out + (size_t)(r0 + 8) * U_DIM + cb) = v1;
        }
    }
}

// ---------------------------------------------------------------- host side
extern "C" void kernel_launch(void* const* d_in, const int* in_sizes, int n_in,
                              void* d_out, int out_size) {
    const float* x    = (const float*)d_in[0];
    const float* kv   = (const float*)d_in[1];
    const float* bias = (const float*)d_in[2];
    const int*   ind  = (const int*)d_in[3];
    float* out = (float*)d_out;
    int nnz = in_sizes[1];

    void* wptr = nullptr;
    void* xptr = nullptr;
    cudaGetSymbolAddress(&wptr, g_W);
    cudaGetSymbolAddress(&xptr, g_X);

    cudaFuncSetAttribute(sparse_gemm_kernel,
                         cudaFuncAttributeMaxDynamicSharedMemorySize, SMEM_DYN);

    cudaMemsetAsync(wptr, 0, (size_t)U_DIM * D_DIM * sizeof(__half));

    int n4 = B_ROWS * D_DIM / 4;
    conv_x_kernel<<<(n4 + 255) / 256, 256>>>((const float4*)x, (uint2*)xptr, n4);

    scatter_kernel<<<(nnz + 255) / 256, 256>>>((const int2*)ind, kv, (__half*)wptr, nnz);

    sparse_gemm_kernel<<<(B_ROWS / MT) * (U_DIM / NT), 256, SMEM_DYN>>>(
        (const __half*)xptr, (const __half*)wptr, bias, out);
}